// round 12
// baseline (speedup 1.0000x reference)
#include <cuda_runtime.h>
#include <cuda_bf16.h>
#include <cstdint>
#include <cstddef>

#define NSEQ 1024
#define DIM  1024
#define BATCH 4
#define HEADS 16
#define DK 64
#define LAYERS 4

// ---------------- fp32 scratch ----------------
__device__ float g_x[BATCH * DIM * NSEQ];        // running x  (c,n)
__device__ float g_m[BATCH * DIM * NSEQ];        // merged (c,n)
__device__ float g_h[BATCH * 2 * DIM * NSEQ];    // hidden after BN/ReLU (c,n)

// ---------------- bf16 buffers ----------------
// combined QKV weights: [layer][3*D][D], rows permuted o'=h*64+dk
__device__ __align__(256) __nv_bfloat16 g_Wqkvh[LAYERS * 3 * DIM * DIM];
__device__ __align__(256) __nv_bfloat16 g_Wqkvl[LAYERS * 3 * DIM * DIM];
__device__ __align__(256) __nv_bfloat16 g_Wmh[LAYERS * DIM * DIM];
__device__ __align__(256) __nv_bfloat16 g_Wml[LAYERS * DIM * DIM];
__device__ __align__(256) __nv_bfloat16 g_Wp1h[LAYERS * 2 * DIM * 2 * DIM];
__device__ __align__(256) __nv_bfloat16 g_Wp1l[LAYERS * 2 * DIM * 2 * DIM];
__device__ __align__(256) __nv_bfloat16 g_Wp2h[LAYERS * DIM * 2 * DIM];
__device__ __align__(256) __nv_bfloat16 g_Wp2l[LAYERS * DIM * 2 * DIM];
__device__ float g_bqkvP[LAYERS * 3 * DIM];
// activations
__device__ __align__(256) __nv_bfloat16 g_xTh[BATCH * NSEQ * DIM];
__device__ __align__(256) __nv_bfloat16 g_xTl[BATCH * NSEQ * DIM];
__device__ __align__(256) __nv_bfloat16 g_qkvh[BATCH * 3 * DIM * NSEQ]; // [b][3D: q|k|v][n]
__device__ __align__(256) __nv_bfloat16 g_qkvl[BATCH * 3 * DIM * NSEQ];
__device__ __align__(256) __nv_bfloat16 g_aTh[BATCH * NSEQ * DIM];  // flash out [b][n][h*64+dk]
__device__ __align__(256) __nv_bfloat16 g_aTl[BATCH * NSEQ * DIM];
__device__ __align__(256) __nv_bfloat16 g_mTh[BATCH * NSEQ * DIM];  // merged^T
__device__ __align__(256) __nv_bfloat16 g_mTl[BATCH * NSEQ * DIM];
__device__ __align__(256) __nv_bfloat16 g_hTh[BATCH * NSEQ * 2 * DIM];
__device__ __align__(256) __nv_bfloat16 g_hTl[BATCH * NSEQ * 2 * DIM];

// ======================= PTX helpers =======================
__device__ __forceinline__ uint32_t smem_u32(const void* p) {
    uint32_t a;
    asm("{ .reg .u64 t; cvta.to.shared.u64 t, %1; cvt.u32.u64 %0, t; }" : "=r"(a) : "l"(p));
    return a;
}
#define CP_ASYNC16(dst, src) \
    asm volatile("cp.async.cg.shared.global [%0], [%1], 16;" :: "r"(dst), "l"(src) : "memory")
#define CP_COMMIT()   asm volatile("cp.async.commit_group;" ::: "memory")
#define CP_WAIT(N)    asm volatile("cp.async.wait_group %0;" :: "n"(N) : "memory")
#define LDM4(r, addr) \
    asm volatile("ldmatrix.sync.aligned.m8n8.x4.shared.b16 {%0,%1,%2,%3}, [%4];" \
        : "=r"((r)[0]), "=r"((r)[1]), "=r"((r)[2]), "=r"((r)[3]) : "r"(addr))
#define LDM4T(r, addr) \
    asm volatile("ldmatrix.sync.aligned.m8n8.x4.trans.shared.b16 {%0,%1,%2,%3}, [%4];" \
        : "=r"((r)[0]), "=r"((r)[1]), "=r"((r)[2]), "=r"((r)[3]) : "r"(addr))
#define MMA_BF16(d, a, b0, b1) \
    asm volatile("mma.sync.aligned.m16n8k16.row.col.f32.bf16.bf16.f32 " \
        "{%0,%1,%2,%3}, {%4,%5,%6,%7}, {%8,%9}, {%0,%1,%2,%3};" \
        : "+f"((d)[0]), "+f"((d)[1]), "+f"((d)[2]), "+f"((d)[3]) \
        : "r"((a)[0]), "r"((a)[1]), "r"((a)[2]), "r"((a)[3]), "r"(b0), "r"(b1))

__device__ __forceinline__ uint32_t packbf(float a, float b) {
    __nv_bfloat16 ha = __float2bfloat16(a), hb = __float2bfloat16(b);
    return (uint32_t)__bfloat16_as_ushort(ha) | ((uint32_t)__bfloat16_as_ushort(hb) << 16);
}

// ======================= tensor GEMM (3x bf16 split, mma.sync) =======================
// out[b, o, n] = sum_c W[o,c] * X[b,n,c]
// B-side activation may come from TWO buffers: chunks [0,NC1) from Xh/Xl,
// chunks [NC1,NC) from Xh2/Xl2 (both row-stride CinB). Weight row-stride = Cin.
#define SROW   40
#define MATB   (128 * SROW * 2)
#define STAGEB (4 * MATB)
#define GSMEM  (2 * STAGEB)

template<int EPI>
__global__ __launch_bounds__(256) void gemmt_k(
    const __nv_bfloat16* __restrict__ Wh, const __nv_bfloat16* __restrict__ Wl,
    const __nv_bfloat16* __restrict__ Xh, const __nv_bfloat16* __restrict__ Xl,
    const __nv_bfloat16* __restrict__ Xh2, const __nv_bfloat16* __restrict__ Xl2,
    const float* __restrict__ bias, float* __restrict__ out,
    __nv_bfloat16* __restrict__ outH, __nv_bfloat16* __restrict__ outL,
    int Cout, int Cin, int CinB, int NC1,
    const float* __restrict__ g, const float* __restrict__ bt,
    const float* __restrict__ mu, const float* __restrict__ var,
    const float* __restrict__ res)
{
    extern __shared__ __align__(16) char sm[];
    const int tid = threadIdx.x;
    const int l = tid & 31, wid = tid >> 5;
    const int wm = wid & 1, wn = wid >> 1;
    const int b = blockIdx.z, n0 = blockIdx.x * 128, o0 = blockIdx.y * 128;

    const __nv_bfloat16* WhB = Wh + (size_t)o0 * Cin;
    const __nv_bfloat16* WlB = Wl + (size_t)o0 * Cin;
    const size_t xoff = ((size_t)b * NSEQ + n0) * CinB;
    const __nv_bfloat16* XhB  = Xh + xoff;
    const __nv_bfloat16* XlB  = Xl + xoff;
    const __nv_bfloat16* Xh2B = Xh2 + xoff;
    const __nv_bfloat16* Xl2B = Xl2 + xoff;

    const uint32_t sbase = smem_u32(sm);
    const int NC = Cin >> 5;

    const int rowA = l & 15;
    const int colA = (l >> 4) << 3;
    int aoff[4];
    #pragma unroll
    for (int mt = 0; mt < 4; mt++)
        aoff[mt] = ((wm * 64 + mt * 16 + rowA) * SROW + colA) * 2;
    int boff[2];
    #pragma unroll
    for (int ntp = 0; ntp < 2; ntp++)
        boff[ntp] = ((wn * 32 + ntp * 16 + ((l >> 4) & 1) * 8 + (l & 7)) * SROW
                     + ((l >> 3) & 1) * 8) * 2;

    float acc[4][4][4];
    #pragma unroll
    for (int i = 0; i < 4; i++)
        #pragma unroll
        for (int j = 0; j < 4; j++)
            #pragma unroll
            for (int q = 0; q < 4; q++) acc[i][j][q] = 0.f;

    auto load = [&](int kc) {
        char* base = sm + (kc & 1) * STAGEB;
        const bool first = kc < NC1;
        const int kco = first ? kc : kc - NC1;
        const __nv_bfloat16* bh = (first ? XhB : Xh2B) + kco * 32;
        const __nv_bfloat16* bl = (first ? XlB : Xl2B) + kco * 32;
        const __nv_bfloat16* wh = WhB + kc * 32;
        const __nv_bfloat16* wl = WlB + kc * 32;
        #pragma unroll
        for (int i = 0; i < 2; i++) {
            int s = tid * 2 + i;
            int row = s >> 2, seg = s & 3;
            uint32_t d0 = smem_u32(base + row * (SROW * 2) + seg * 16);
            CP_ASYNC16(d0,            wh + (size_t)row * Cin  + seg * 8);
            CP_ASYNC16(d0 + MATB,     wl + (size_t)row * Cin  + seg * 8);
            CP_ASYNC16(d0 + 2 * MATB, bh + (size_t)row * CinB + seg * 8);
            CP_ASYNC16(d0 + 3 * MATB, bl + (size_t)row * CinB + seg * 8);
        }
        CP_COMMIT();
    };

    load(0);
    for (int kc = 0; kc < NC; kc++) {
        if (kc + 1 < NC) { load(kc + 1); CP_WAIT(1); }
        else            { CP_WAIT(0); }
        __syncthreads();

        const uint32_t S = sbase + (kc & 1) * STAGEB;
        #pragma unroll
        for (int ks = 0; ks < 2; ks++) {
            unsigned fa[4][4], fbh[2][4], fbl[2][4];
            #pragma unroll
            for (int mt = 0; mt < 4; mt++) LDM4(fa[mt], S + aoff[mt] + ks * 32);
            #pragma unroll
            for (int p = 0; p < 2; p++) {
                LDM4(fbh[p], S + 2 * MATB + boff[p] + ks * 32);
                LDM4(fbl[p], S + 3 * MATB + boff[p] + ks * 32);
            }
            #pragma unroll
            for (int mt = 0; mt < 4; mt++)
                #pragma unroll
                for (int nt = 0; nt < 4; nt++) {
                    MMA_BF16(acc[mt][nt], fa[mt], fbh[nt >> 1][(nt & 1) * 2],
                             fbh[nt >> 1][(nt & 1) * 2 + 1]);
                    MMA_BF16(acc[mt][nt], fa[mt], fbl[nt >> 1][(nt & 1) * 2],
                             fbl[nt >> 1][(nt & 1) * 2 + 1]);
                }
            #pragma unroll
            for (int mt = 0; mt < 4; mt++) LDM4(fa[mt], S + MATB + aoff[mt] + ks * 32);
            #pragma unroll
            for (int mt = 0; mt < 4; mt++)
                #pragma unroll
                for (int nt = 0; nt < 4; nt++)
                    MMA_BF16(acc[mt][nt], fa[mt], fbh[nt >> 1][(nt & 1) * 2],
                             fbh[nt >> 1][(nt & 1) * 2 + 1]);
        }
        __syncthreads();
    }

    // ---------------- epilogue ----------------
    #pragma unroll
    for (int mt = 0; mt < 4; mt++) {
        int o1 = o0 + wm * 64 + mt * 16 + (l >> 2);
        int o2 = o1 + 8;
        float b1v = bias[o1], b2v = bias[o2];
        float sc1 = 1.f, sh1 = 0.f, sc2 = 1.f, sh2 = 0.f;
        if (EPI == 1) {
            float s1 = g[o1] * rsqrtf(var[o1] + 1e-5f);
            sc1 = s1; sh1 = bt[o1] - mu[o1] * s1;
            float s2 = g[o2] * rsqrtf(var[o2] + 1e-5f);
            sc2 = s2; sh2 = bt[o2] - mu[o2] * s2;
        }
        size_t r1i = ((size_t)b * Cout + o1) * NSEQ + n0 + wn * 32;
        size_t r2i = ((size_t)b * Cout + o2) * NSEQ + n0 + wn * 32;
        #pragma unroll
        for (int nt = 0; nt < 4; nt++) {
            int nn = nt * 8 + (l & 3) * 2;
            float v0 = acc[mt][nt][0] + b1v, v1 = acc[mt][nt][1] + b1v;
            float v2 = acc[mt][nt][2] + b2v, v3 = acc[mt][nt][3] + b2v;
            if (EPI == 1) {
                v0 = fmaxf(fmaf(v0, sc1, sh1), 0.f); v1 = fmaxf(fmaf(v1, sc1, sh1), 0.f);
                v2 = fmaxf(fmaf(v2, sc2, sh2), 0.f); v3 = fmaxf(fmaf(v3, sc2, sh2), 0.f);
            }
            if (EPI == 2) {
                float2 ra = *(const float2*)(res + r1i + nn);
                float2 rb = *(const float2*)(res + r2i + nn);
                v0 += ra.x; v1 += ra.y; v2 += rb.x; v3 += rb.y;
            }
            if (EPI == 3) {
                __nv_bfloat16 h0 = __float2bfloat16(v0), h1 = __float2bfloat16(v1);
                __nv_bfloat16 h2 = __float2bfloat16(v2), h3 = __float2bfloat16(v3);
                uint32_t H1 = (uint32_t)__bfloat16_as_ushort(h0) | ((uint32_t)__bfloat16_as_ushort(h1) << 16);
                uint32_t H2 = (uint32_t)__bfloat16_as_ushort(h2) | ((uint32_t)__bfloat16_as_ushort(h3) << 16);
                uint32_t L1 = packbf(v0 - __bfloat162float(h0), v1 - __bfloat162float(h1));
                uint32_t L2 = packbf(v2 - __bfloat162float(h2), v3 - __bfloat162float(h3));
                *(uint32_t*)(outH + r1i + nn) = H1;
                *(uint32_t*)(outH + r2i + nn) = H2;
                *(uint32_t*)(outL + r1i + nn) = L1;
                *(uint32_t*)(outL + r2i + nn) = L2;
            } else {
                *(float2*)(out + r1i + nn) = make_float2(v0, v1);
                *(float2*)(out + r2i + nn) = make_float2(v2, v3);
            }
        }
    }
}

// ======================= flash attention (mma.sync, 3x split) =======================
// QKV combined: [b][3D: q|k|v][n], per head [dk][n].
// Output: [b][n][h*64+dk] bf16 hi/lo.
#define FSROW 136
#define FROWB (FSROW * 2)        // 272 B
#define FMATB (64 * FROWB)       // 17408 B
#define FSMEM (10 * FMATB)       // 174080 B

__global__ __launch_bounds__(256, 1) void flash_k(
    const __nv_bfloat16* __restrict__ QKVh, const __nv_bfloat16* __restrict__ QKVl,
    __nv_bfloat16* __restrict__ Oh, __nv_bfloat16* __restrict__ Ol)
{
    extern __shared__ __align__(16) char sm[];
    const int tid = threadIdx.x, l = tid & 31, w = tid >> 5;
    const int n0 = blockIdx.x * 128;
    const int bh = blockIdx.y;
    const int b = bh >> 4, h = bh & 15;
    const size_t qbase = ((size_t)b * 3 * DIM + h * 64) * NSEQ;
    const size_t kbase = qbase + (size_t)DIM * NSEQ;
    const size_t vbase = kbase + (size_t)DIM * NSEQ;
    const uint32_t sb = smem_u32(sm);

    // ---- q load ----
    {
        const __nv_bfloat16* srcs[2] = {QKVh + qbase + n0, QKVl + qbase + n0};
        #pragma unroll
        for (int m4 = 0; m4 < 2; m4++)
            #pragma unroll
            for (int i = 0; i < 4; i++) {
                int idx = tid + i * 256;
                int row = idx >> 4, seg = idx & 15;
                CP_ASYNC16(sb + m4 * FMATB + row * FROWB + seg * 16,
                           (const char*)(srcs[m4] + (size_t)row * NSEQ) + seg * 16);
            }
    }
    auto load_kv = [&](int kc) {
        int m0 = kc * 128;
        const __nv_bfloat16* srcs[4] = {QKVh + kbase + m0, QKVl + kbase + m0,
                                        QKVh + vbase + m0, QKVl + vbase + m0};
        uint32_t stg = sb + 2 * FMATB + (kc & 1) * 4 * FMATB;
        #pragma unroll
        for (int m4 = 0; m4 < 4; m4++)
            #pragma unroll
            for (int i = 0; i < 4; i++) {
                int idx = tid + i * 256;
                int row = idx >> 4, seg = idx & 15;
                CP_ASYNC16(stg + m4 * FMATB + row * FROWB + seg * 16,
                           (const char*)(srcs[m4] + (size_t)row * NSEQ) + seg * 16);
            }
    };
    load_kv(0); CP_COMMIT();
    load_kv(1); CP_COMMIT();
    CP_WAIT(1); __syncthreads();

    // ---- preload Q a-frags ----
    unsigned qfh[4][4], qfl[4][4];
    {
        int row_in = ((l >> 4) & 1) * 8 + (l & 7);
        int col = w * 16 + ((l >> 3) & 1) * 8;
        #pragma unroll
        for (int ks = 0; ks < 4; ks++) {
            uint32_t a = sb + (ks * 16 + row_in) * FROWB + col * 2;
            LDM4T(qfh[ks], a);
            LDM4T(qfl[ks], a + FMATB);
        }
    }

    float Oacc[8][4];
    #pragma unroll
    for (int u = 0; u < 8; u++)
        #pragma unroll
        for (int q = 0; q < 4; q++) Oacc[u][q] = 0.f;
    float rm0 = -1e30f, rm1 = -1e30f, rs0 = 0.f, rs1 = 0.f;

    const int krow = ((l >> 3) & 1) * 8 + (l & 7);
    const int kcol = ((l >> 4) & 1) * 8;
    const int vrow = ((l >> 4) & 1) * 8 + (l & 7);
    const int vcol = ((l >> 3) & 1) * 8;

    for (int kc = 0; kc < 8; kc++) {
        uint32_t stg = sb + 2 * FMATB + (kc & 1) * 4 * FMATB;

        float sacc[16][4];
        #pragma unroll
        for (int t = 0; t < 16; t++)
            #pragma unroll
            for (int q = 0; q < 4; q++) sacc[t][q] = 0.f;

        #pragma unroll
        for (int j = 0; j < 8; j++) {
            #pragma unroll
            for (int ks = 0; ks < 4; ks++) {
                unsigned bh4[4], bl4[4];
                uint32_t a = stg + (ks * 16 + krow) * FROWB + (j * 16 + kcol) * 2;
                LDM4T(bh4, a);
                LDM4T(bl4, a + FMATB);
                MMA_BF16(sacc[2 * j],     qfh[ks], bh4[0], bh4[1]);
                MMA_BF16(sacc[2 * j + 1], qfh[ks], bh4[2], bh4[3]);
                MMA_BF16(sacc[2 * j],     qfh[ks], bl4[0], bl4[1]);
                MMA_BF16(sacc[2 * j + 1], qfh[ks], bl4[2], bl4[3]);
                MMA_BF16(sacc[2 * j],     qfl[ks], bh4[0], bh4[1]);
                MMA_BF16(sacc[2 * j + 1], qfl[ks], bh4[2], bh4[3]);
            }
        }

        // ---- online softmax ----
        float cm0 = -1e30f, cm1 = -1e30f;
        #pragma unroll
        for (int t = 0; t < 16; t++) {
            sacc[t][0] *= 0.125f; sacc[t][1] *= 0.125f;
            sacc[t][2] *= 0.125f; sacc[t][3] *= 0.125f;
            cm0 = fmaxf(cm0, fmaxf(sacc[t][0], sacc[t][1]));
            cm1 = fmaxf(cm1, fmaxf(sacc[t][2], sacc[t][3]));
        }
        cm0 = fmaxf(cm0, __shfl_xor_sync(0xffffffffu, cm0, 1));
        cm0 = fmaxf(cm0, __shfl_xor_sync(0xffffffffu, cm0, 2));
        cm1 = fmaxf(cm1, __shfl_xor_sync(0xffffffffu, cm1, 1));
        cm1 = fmaxf(cm1, __shfl_xor_sync(0xffffffffu, cm1, 2));
        float nm0 = fmaxf(rm0, cm0), nm1 = fmaxf(rm1, cm1);
        float al0 = __expf(rm0 - nm0), al1 = __expf(rm1 - nm1);
        rm0 = nm0; rm1 = nm1;

        float cs0 = 0.f, cs1 = 0.f;
        #pragma unroll
        for (int t = 0; t < 16; t++) {
            sacc[t][0] = __expf(sacc[t][0] - nm0);
            sacc[t][1] = __expf(sacc[t][1] - nm0);
            sacc[t][2] = __expf(sacc[t][2] - nm1);
            sacc[t][3] = __expf(sacc[t][3] - nm1);
            cs0 += sacc[t][0] + sacc[t][1];
            cs1 += sacc[t][2] + sacc[t][3];
        }
        cs0 += __shfl_xor_sync(0xffffffffu, cs0, 1);
        cs0 += __shfl_xor_sync(0xffffffffu, cs0, 2);
        cs1 += __shfl_xor_sync(0xffffffffu, cs1, 1);
        cs1 += __shfl_xor_sync(0xffffffffu, cs1, 2);
        rs0 = rs0 * al0 + cs0;
        rs1 = rs1 * al1 + cs1;
        #pragma unroll
        for (int u = 0; u < 8; u++) {
            Oacc[u][0] *= al0; Oacc[u][1] *= al0;
            Oacc[u][2] *= al1; Oacc[u][3] *= al1;
        }

        // ---- O += P V ----
        #pragma unroll
        for (int kk = 0; kk < 8; kk++) {
            unsigned pfh[4], pfl[4];
            {
                float p0 = sacc[2 * kk][0],     p1 = sacc[2 * kk][1];
                float p2 = sacc[2 * kk][2],     p3 = sacc[2 * kk][3];
                float p4 = sacc[2 * kk + 1][0], p5 = sacc[2 * kk + 1][1];
                float p6 = sacc[2 * kk + 1][2], p7 = sacc[2 * kk + 1][3];
                __nv_bfloat16 h0 = __float2bfloat16(p0), h1 = __float2bfloat16(p1);
                __nv_bfloat16 h2 = __float2bfloat16(p2), h3 = __float2bfloat16(p3);
                __nv_bfloat16 h4 = __float2bfloat16(p4), h5 = __float2bfloat16(p5);
                __nv_bfloat16 h6 = __float2bfloat16(p6), h7 = __float2bfloat16(p7);
                pfh[0] = (uint32_t)__bfloat16_as_ushort(h0) | ((uint32_t)__bfloat16_as_ushort(h1) << 16);
                pfh[1] = (uint32_t)__bfloat16_as_ushort(h2) | ((uint32_t)__bfloat16_as_ushort(h3) << 16);
                pfh[2] = (uint32_t)__bfloat16_as_ushort(h4) | ((uint32_t)__bfloat16_as_ushort(h5) << 16);
                pfh[3] = (uint32_t)__bfloat16_as_ushort(h6) | ((uint32_t)__bfloat16_as_ushort(h7) << 16);
                pfl[0] = packbf(p0 - __bfloat162float(h0), p1 - __bfloat162float(h1));
                pfl[1] = packbf(p2 - __bfloat162float(h2), p3 - __bfloat162float(h3));
                pfl[2] = packbf(p4 - __bfloat162float(h4), p5 - __bfloat162float(h5));
                pfl[3] = packbf(p6 - __bfloat162float(h6), p7 - __bfloat162float(h7));
            }
            #pragma unroll
            for (int t = 0; t < 4; t++) {
                unsigned vh4[4], vl4[4];
                uint32_t a = stg + 2 * FMATB + (t * 16 + vrow) * FROWB + (kk * 16 + vcol) * 2;
                LDM4(vh4, a);
                LDM4(vl4, a + FMATB);
                MMA_BF16(Oacc[2 * t],     pfh, vh4[0], vh4[1]);
                MMA_BF16(Oacc[2 * t + 1], pfh, vh4[2], vh4[3]);
                MMA_BF16(Oacc[2 * t],     pfl, vh4[0], vh4[1]);
                MMA_BF16(Oacc[2 * t + 1], pfl, vh4[2], vh4[3]);
                MMA_BF16(Oacc[2 * t],     pfh, vl4[0], vl4[1]);
                MMA_BF16(Oacc[2 * t + 1], pfh, vl4[2], vl4[3]);
            }
        }
        __syncthreads();
        if (kc + 2 < 8) {
            load_kv(kc + 2); CP_COMMIT();
            CP_WAIT(1); __syncthreads();
        } else if (kc + 1 < 8) {
            CP_WAIT(0); __syncthreads();
        }
    }

    // ---- finalize ----
    float inv0 = 1.f / rs0, inv1 = 1.f / rs1;
    int nr0 = n0 + w * 16 + (l >> 2);
    int nr1 = nr0 + 8;
    size_t base0 = ((size_t)b * NSEQ + nr0) * DIM + h * 64;
    size_t base1 = ((size_t)b * NSEQ + nr1) * DIM + h * 64;
    #pragma unroll
    for (int u = 0; u < 8; u++) {
        int dk = u * 8 + 2 * (l & 3);
        float v0 = Oacc[u][0] * inv0, v1 = Oacc[u][1] * inv0;
        float v2 = Oacc[u][2] * inv1, v3 = Oacc[u][3] * inv1;
        __nv_bfloat16 h0 = __float2bfloat16(v0), h1 = __float2bfloat16(v1);
        __nv_bfloat16 h2 = __float2bfloat16(v2), h3 = __float2bfloat16(v3);
        *(uint32_t*)(Oh + base0 + dk) =
            (uint32_t)__bfloat16_as_ushort(h0) | ((uint32_t)__bfloat16_as_ushort(h1) << 16);
        *(uint32_t*)(Oh + base1 + dk) =
            (uint32_t)__bfloat16_as_ushort(h2) | ((uint32_t)__bfloat16_as_ushort(h3) << 16);
        *(uint32_t*)(Ol + base0 + dk) = packbf(v0 - __bfloat162float(h0), v1 - __bfloat162float(h1));
        *(uint32_t*)(Ol + base1 + dk) = packbf(v2 - __bfloat162float(h2), v3 - __bfloat162float(h3));
    }
}

// ======================= weight split kernels =======================
__global__ __launch_bounds__(256) void split_k(
    const float* __restrict__ src, __nv_bfloat16* __restrict__ hi,
    __nv_bfloat16* __restrict__ lo, int n4)
{
    int i = blockIdx.x * 256 + threadIdx.x;
    if (i >= n4) return;
    float4 v = ((const float4*)src)[i];
    __nv_bfloat16 hx = __float2bfloat16(v.x), hy = __float2bfloat16(v.y);
    __nv_bfloat16 hz = __float2bfloat16(v.z), hw = __float2bfloat16(v.w);
    uint2 H, L;
    H.x = (uint32_t)__bfloat16_as_ushort(hx) | ((uint32_t)__bfloat16_as_ushort(hy) << 16);
    H.y = (uint32_t)__bfloat16_as_ushort(hz) | ((uint32_t)__bfloat16_as_ushort(hw) << 16);
    L.x = packbf(v.x - __bfloat162float(hx), v.y - __bfloat162float(hy));
    L.y = packbf(v.z - __bfloat162float(hz), v.w - __bfloat162float(hw));
    ((uint2*)hi)[i] = H;
    ((uint2*)lo)[i] = L;
}

// row-permuted split into combined QKV buffer region `reg`:
// dst[layer][reg*D + o'][c],  o' = h*64+dk  <-  src[layer][dk*16+h][c]
__global__ __launch_bounds__(256) void split_permR_k(
    const float* __restrict__ src, __nv_bfloat16* __restrict__ hi,
    __nv_bfloat16* __restrict__ lo, int reg)
{
    int i = blockIdx.x * 256 + threadIdx.x;      // over L*D*(D/4)
    int row = i / (DIM / 4), c4 = i % (DIM / 4);
    int layer = row / DIM, op = row % DIM;
    int o = ((op & 63) << 4) + (op >> 6);
    float4 v = ((const float4*)src)[((size_t)layer * DIM + o) * (DIM / 4) + c4];
    __nv_bfloat16 hx = __float2bfloat16(v.x), hy = __float2bfloat16(v.y);
    __nv_bfloat16 hz = __float2bfloat16(v.z), hw = __float2bfloat16(v.w);
    uint2 H, L;
    H.x = (uint32_t)__bfloat16_as_ushort(hx) | ((uint32_t)__bfloat16_as_ushort(hy) << 16);
    H.y = (uint32_t)__bfloat16_as_ushort(hz) | ((uint32_t)__bfloat16_as_ushort(hw) << 16);
    L.x = packbf(v.x - __bfloat162float(hx), v.y - __bfloat162float(hy));
    L.y = packbf(v.z - __bfloat162float(hz), v.w - __bfloat162float(hw));
    size_t j = (((size_t)layer * 3 + reg) * DIM + op) * (DIM / 4) + c4;
    ((uint2*)hi)[j] = H;
    ((uint2*)lo)[j] = L;
}

// col-permuted split: out[layer, o, c'=h*64+dk] = in[layer, o, dk*16+h]
__global__ __launch_bounds__(256) void split_permC_k(
    const float* __restrict__ src, __nv_bfloat16* __restrict__ hi,
    __nv_bfloat16* __restrict__ lo)
{
    int i = blockIdx.x * 256 + threadIdx.x;
    int row = i / DIM, cp = i % DIM;
    int c = ((cp & 63) << 4) + (cp >> 6);
    float v = src[(size_t)row * DIM + c];
    __nv_bfloat16 hv = __float2bfloat16(v);
    hi[i] = hv;
    lo[i] = __float2bfloat16(v - __bfloat162float(hv));
}

__global__ __launch_bounds__(256) void permB_k(
    const float* __restrict__ src, float* __restrict__ dst, int reg)
{
    int i = blockIdx.x * 256 + threadIdx.x;      // over L*D
    int layer = i / DIM, op = i % DIM;
    dst[((size_t)layer * 3 + reg) * DIM + op] =
        src[layer * DIM + ((op & 63) << 4) + (op >> 6)];
}

// ======================= transpose + split =======================
__global__ __launch_bounds__(256) void transposeS_k(
    const float* __restrict__ src, __nv_bfloat16* __restrict__ dstH,
    __nv_bfloat16* __restrict__ dstL, int C, int dstStride, int dstOff)
{
    __shared__ float t[32][33];
    const int b  = blockIdx.z;
    const int n0 = blockIdx.x * 32;
    const int c0 = blockIdx.y * 32;
    const float* s = src + (size_t)b * C * NSEQ;
    const size_t dbase = (size_t)b * NSEQ * dstStride + dstOff;
    const int tx = threadIdx.x & 31, ty = threadIdx.x >> 5;
    #pragma unroll
    for (int i = 0; i < 32; i += 8)
        t[ty + i][tx] = s[(size_t)(c0 + ty + i) * NSEQ + n0 + tx];
    __syncthreads();
    #pragma unroll
    for (int i = 0; i < 32; i += 8) {
        float v = t[tx][ty + i];
        __nv_bfloat16 hv = __float2bfloat16(v);
        size_t idx = dbase + (size_t)(n0 + ty + i) * dstStride + c0 + tx;
        dstH[idx] = hv;
        dstL[idx] = __float2bfloat16(v - __bfloat162float(hv));
    }
}

// ======================= host launcher =======================
extern "C" void kernel_launch(void* const* d_in, const int* in_sizes, int n_in,
                              void* d_out, int out_size)
{
    const float* motion = (const float*)d_in[0];
    const float* Wq  = (const float*)d_in[1];
    const float* bq  = (const float*)d_in[2];
    const float* Wk  = (const float*)d_in[3];
    const float* bk  = (const float*)d_in[4];
    const float* Wv  = (const float*)d_in[5];
    const float* bv  = (const float*)d_in[6];
    const float* Wm  = (const float*)d_in[7];
    const float* bm  = (const float*)d_in[8];
    const float* Wp1 = (const float*)d_in[9];
    const float* bp1 = (const float*)d_in[10];
    const float* bng = (const float*)d_in[11];
    const float* bnb = (const float*)d_in[12];
    const float* bnm = (const float*)d_in[13];
    const float* bnv = (const float*)d_in[14];
    const float* Wp2 = (const float*)d_in[15];
    const float* bp2 = (const float*)d_in[16];

    float *xb, *mb, *hb, *bqkvP;
    cudaGetSymbolAddress((void**)&xb, g_x);
    cudaGetSymbolAddress((void**)&mb, g_m);
    cudaGetSymbolAddress((void**)&hb, g_h);
    cudaGetSymbolAddress((void**)&bqkvP, g_bqkvP);

    __nv_bfloat16 *Wqkvh, *Wqkvl, *Wmh, *Wml, *Wp1h, *Wp1l, *Wp2h, *Wp2l;
    __nv_bfloat16 *xTh, *xTl, *aTh, *aTl, *mTh, *mTl, *hTh, *hTl, *qkvh, *qkvl;
    cudaGetSymbolAddress((void**)&Wqkvh, g_Wqkvh); cudaGetSymbolAddress((void**)&Wqkvl, g_Wqkvl);
    cudaGetSymbolAddress((void**)&Wmh, g_Wmh);     cudaGetSymbolAddress((void**)&Wml, g_Wml);
    cudaGetSymbolAddress((void**)&Wp1h, g_Wp1h);   cudaGetSymbolAddress((void**)&Wp1l, g_Wp1l);
    cudaGetSymbolAddress((void**)&Wp2h, g_Wp2h);   cudaGetSymbolAddress((void**)&Wp2l, g_Wp2l);
    cudaGetSymbolAddress((void**)&xTh, g_xTh);     cudaGetSymbolAddress((void**)&xTl, g_xTl);
    cudaGetSymbolAddress((void**)&aTh, g_aTh);     cudaGetSymbolAddress((void**)&aTl, g_aTl);
    cudaGetSymbolAddress((void**)&mTh, g_mTh);     cudaGetSymbolAddress((void**)&mTl, g_mTl);
    cudaGetSymbolAddress((void**)&hTh, g_hTh);     cudaGetSymbolAddress((void**)&hTl, g_hTl);
    cudaGetSymbolAddress((void**)&qkvh, g_qkvh);   cudaGetSymbolAddress((void**)&qkvl, g_qkvl);

    cudaFuncSetAttribute(gemmt_k<0>, cudaFuncAttributeMaxDynamicSharedMemorySize, GSMEM);
    cudaFuncSetAttribute(gemmt_k<1>, cudaFuncAttributeMaxDynamicSharedMemorySize, GSMEM);
    cudaFuncSetAttribute(gemmt_k<2>, cudaFuncAttributeMaxDynamicSharedMemorySize, GSMEM);
    cudaFuncSetAttribute(gemmt_k<3>, cudaFuncAttributeMaxDynamicSharedMemorySize, GSMEM);
    cudaFuncSetAttribute(flash_k, cudaFuncAttributeMaxDynamicSharedMemorySize, FSMEM);

    cudaMemcpyAsync(xb, motion, (size_t)BATCH * DIM * NSEQ * sizeof(float),
                    cudaMemcpyDeviceToDevice);

    // ---- weight prep ----
    const int nW  = LAYERS * DIM * DIM;
    const int nP1 = LAYERS * 2 * DIM * 2 * DIM;
    const int nP2 = LAYERS * DIM * 2 * DIM;
    split_permR_k<<<nW / 4 / 256, 256>>>(Wq, Wqkvh, Wqkvl, 0);
    split_permR_k<<<nW / 4 / 256, 256>>>(Wk, Wqkvh, Wqkvl, 1);
    split_permR_k<<<nW / 4 / 256, 256>>>(Wv, Wqkvh, Wqkvl, 2);
    split_permC_k<<<nW / 256, 256>>>(Wm, Wmh, Wml);
    split_k<<<(nP1 / 4 + 255) / 256, 256>>>(Wp1, Wp1h, Wp1l, nP1 / 4);
    split_k<<<(nP2 / 4 + 255) / 256, 256>>>(Wp2, Wp2h, Wp2l, nP2 / 4);
    permB_k<<<LAYERS * DIM / 256, 256>>>(bq, bqkvP, 0);
    permB_k<<<LAYERS * DIM / 256, 256>>>(bk, bqkvP, 1);
    permB_k<<<LAYERS * DIM / 256, 256>>>(bv, bqkvP, 2);

    const size_t DD  = (size_t)DIM * DIM;
    const size_t DD2 = (size_t)2 * DIM * 2 * DIM;
    const size_t DD3 = (size_t)DIM * 2 * DIM;

    dim3 gT1(NSEQ / 32, DIM / 32, BATCH);
    dim3 gT2(NSEQ / 32, 2 * DIM / 32, BATCH);
    dim3 gQKV(8, 24, BATCH);      // Cout=3072
    dim3 gGemmD(8, 8, BATCH);     // Cout=1024
    dim3 gGemm2D(8, 16, BATCH);   // Cout=2048
    dim3 gFlash(NSEQ / 128, BATCH * HEADS);

    for (int l = 0; l < LAYERS; l++) {
        transposeS_k<<<gT1, 256>>>(xb, xTh, xTl, DIM, DIM, 0);

        // fused Q|K|V projection -> bf16 hi/lo [b][3D][n]
        gemmt_k<3><<<gQKV, 256, GSMEM>>>(
            Wqkvh + l * 3 * DD, Wqkvl + l * 3 * DD,
            xTh, xTl, xTh, xTl,
            bqkvP + (size_t)l * 3 * DIM, nullptr, qkvh, qkvl,
            3 * DIM, DIM, DIM, 32,
            nullptr, nullptr, nullptr, nullptr, nullptr);

        flash_k<<<gFlash, 256, FSMEM>>>(qkvh, qkvl, aTh, aTl);

        gemmt_k<0><<<gGemmD, 256, GSMEM>>>(
            Wmh + l * DD, Wml + l * DD,
            aTh, aTl, aTh, aTl,
            bm + l * DIM, mb, nullptr, nullptr,
            DIM, DIM, DIM, 32,
            nullptr, nullptr, nullptr, nullptr, nullptr);

        transposeS_k<<<gT1, 256>>>(mb, mTh, mTl, DIM, DIM, 0);

        // P1 reads concat(merged^T | x^T) from two buffers
        gemmt_k<1><<<gGemm2D, 256, GSMEM>>>(
            Wp1h + l * DD2, Wp1l + l * DD2,
            mTh, mTl, xTh, xTl,
            bp1 + (size_t)l * 2 * DIM, hb, nullptr, nullptr,
            2 * DIM, 2 * DIM, DIM, 32,
            bng + l * 2 * DIM, bnb + l * 2 * DIM,
            bnm + l * 2 * DIM, bnv + l * 2 * DIM, nullptr);

        transposeS_k<<<gT2, 256>>>(hb, hTh, hTl, 2 * DIM, 2 * DIM, 0);

        float* dst = (l == LAYERS - 1) ? (float*)d_out : xb;
        gemmt_k<2><<<gGemmD, 256, GSMEM>>>(
            Wp2h + l * DD3, Wp2l + l * DD3,
            hTh, hTl, hTh, hTl,
            bp2 + l * DIM, dst, nullptr, nullptr,
            DIM, 2 * DIM, 2 * DIM, 64,
            nullptr, nullptr, nullptr, nullptr, xb);
    }
}

// round 13
// speedup vs baseline: 1.3130x; 1.3130x over previous
#include <cuda_runtime.h>
#include <cuda_bf16.h>
#include <cuda_fp16.h>
#include <cstdint>
#include <cstddef>

#define NSEQ 1024
#define DIM  1024
#define BATCH 4
#define HEADS 16
#define DK 64
#define LAYERS 4

// ---------------- fp32 scratch ----------------
__device__ float g_x[BATCH * DIM * NSEQ];        // running x  (c,n)
__device__ float g_m[BATCH * DIM * NSEQ];        // merged (c,n)
__device__ float g_h[BATCH * 2 * DIM * NSEQ];    // hidden after BN/ReLU (c,n)

// ---------------- weights: fp16 hi/lo pairs ----------------
__device__ __align__(256) __half g_Wqkvh[LAYERS * 3 * DIM * DIM];
__device__ __align__(256) __half g_Wqkvl[LAYERS * 3 * DIM * DIM];
__device__ __align__(256) __half g_Wmh[LAYERS * DIM * DIM];
__device__ __align__(256) __half g_Wml[LAYERS * DIM * DIM];
__device__ __align__(256) __half g_Wp1h[LAYERS * 2 * DIM * 2 * DIM];
__device__ __align__(256) __half g_Wp1l[LAYERS * 2 * DIM * 2 * DIM];
__device__ __align__(256) __half g_Wp2h[LAYERS * DIM * 2 * DIM];
__device__ __align__(256) __half g_Wp2l[LAYERS * DIM * 2 * DIM];
__device__ float g_bqkvP[LAYERS * 3 * DIM];
// ---------------- activations ----------------
__device__ __align__(256) __half g_xT[BATCH * NSEQ * DIM];            // x^T single fp16
__device__ __align__(256) __nv_bfloat16 g_qkvh[BATCH * 3 * DIM * NSEQ]; // bf16 hi/lo for flash
__device__ __align__(256) __nv_bfloat16 g_qkvl[BATCH * 3 * DIM * NSEQ];
__device__ __align__(256) __half g_aT[BATCH * NSEQ * DIM];            // flash out, single fp16
__device__ __align__(256) __half g_mT[BATCH * NSEQ * DIM];            // merged^T single fp16
__device__ __align__(256) __half g_hT[BATCH * NSEQ * 2 * DIM];        // hidden^T single fp16

// ======================= PTX helpers =======================
__device__ __forceinline__ uint32_t smem_u32(const void* p) {
    uint32_t a;
    asm("{ .reg .u64 t; cvta.to.shared.u64 t, %1; cvt.u32.u64 %0, t; }" : "=r"(a) : "l"(p));
    return a;
}
#define CP_ASYNC16(dst, src) \
    asm volatile("cp.async.cg.shared.global [%0], [%1], 16;" :: "r"(dst), "l"(src) : "memory")
#define CP_COMMIT()   asm volatile("cp.async.commit_group;" ::: "memory")
#define CP_WAIT(N)    asm volatile("cp.async.wait_group %0;" :: "n"(N) : "memory")
#define LDM4(r, addr) \
    asm volatile("ldmatrix.sync.aligned.m8n8.x4.shared.b16 {%0,%1,%2,%3}, [%4];" \
        : "=r"((r)[0]), "=r"((r)[1]), "=r"((r)[2]), "=r"((r)[3]) : "r"(addr))
#define LDM4T(r, addr) \
    asm volatile("ldmatrix.sync.aligned.m8n8.x4.trans.shared.b16 {%0,%1,%2,%3}, [%4];" \
        : "=r"((r)[0]), "=r"((r)[1]), "=r"((r)[2]), "=r"((r)[3]) : "r"(addr))
#define MMA_BF16(d, a, b0, b1) \
    asm volatile("mma.sync.aligned.m16n8k16.row.col.f32.bf16.bf16.f32 " \
        "{%0,%1,%2,%3}, {%4,%5,%6,%7}, {%8,%9}, {%0,%1,%2,%3};" \
        : "+f"((d)[0]), "+f"((d)[1]), "+f"((d)[2]), "+f"((d)[3]) \
        : "r"((a)[0]), "r"((a)[1]), "r"((a)[2]), "r"((a)[3]), "r"(b0), "r"(b1))
#define MMA_FP16(d, a, b0, b1) \
    asm volatile("mma.sync.aligned.m16n8k16.row.col.f32.f16.f16.f32 " \
        "{%0,%1,%2,%3}, {%4,%5,%6,%7}, {%8,%9}, {%0,%1,%2,%3};" \
        : "+f"((d)[0]), "+f"((d)[1]), "+f"((d)[2]), "+f"((d)[3]) \
        : "r"((a)[0]), "r"((a)[1]), "r"((a)[2]), "r"((a)[3]), "r"(b0), "r"(b1))

__device__ __forceinline__ uint32_t packbf(float a, float b) {
    __nv_bfloat16 ha = __float2bfloat16(a), hb = __float2bfloat16(b);
    return (uint32_t)__bfloat16_as_ushort(ha) | ((uint32_t)__bfloat16_as_ushort(hb) << 16);
}
__device__ __forceinline__ uint32_t packh(float a, float b) {
    __half ha = __float2half(a), hb = __float2half(b);
    return (uint32_t)__half_as_ushort(ha) | ((uint32_t)__half_as_ushort(hb) << 16);
}

// ======================= tensor GEMM (fp16 2-pass: W hi/lo split, X single) =======================
// out[b, o, n] = sum_c W[o,c] * X[b,n,c]
// B-side single-fp16 activation; may come from TWO buffers (concat): chunks
// [0,NC1) from Xf, chunks [NC1,NC) from Xf2 (both row-stride CinB).
#define SROW   40
#define MATB   (128 * SROW * 2)      // 10240 B per matrix
#define STAGEB (3 * MATB)            // Wh, Wl, Xf
#define GSMEM  (2 * STAGEB)          // 61440 B

template<int EPI>
__global__ __launch_bounds__(256) void gemmt_k(
    const __half* __restrict__ Wh, const __half* __restrict__ Wl,
    const __half* __restrict__ Xf, const __half* __restrict__ Xf2,
    const float* __restrict__ bias, float* __restrict__ out,
    __nv_bfloat16* __restrict__ outH, __nv_bfloat16* __restrict__ outL,
    int Cout, int Cin, int CinB, int NC1,
    const float* __restrict__ g, const float* __restrict__ bt,
    const float* __restrict__ mu, const float* __restrict__ var,
    const float* __restrict__ res)
{
    extern __shared__ __align__(16) char sm[];
    const int tid = threadIdx.x;
    const int l = tid & 31, wid = tid >> 5;
    const int wm = wid & 1, wn = wid >> 1;
    const int b = blockIdx.z, n0 = blockIdx.x * 128, o0 = blockIdx.y * 128;

    const __half* WhB = Wh + (size_t)o0 * Cin;
    const __half* WlB = Wl + (size_t)o0 * Cin;
    const size_t xoff = ((size_t)b * NSEQ + n0) * CinB;
    const __half* XfB  = Xf + xoff;
    const __half* Xf2B = Xf2 + xoff;

    const uint32_t sbase = smem_u32(sm);
    const int NC = Cin >> 5;

    const int rowA = l & 15;
    const int colA = (l >> 4) << 3;
    int aoff[4];
    #pragma unroll
    for (int mt = 0; mt < 4; mt++)
        aoff[mt] = ((wm * 64 + mt * 16 + rowA) * SROW + colA) * 2;
    int boff[2];
    #pragma unroll
    for (int ntp = 0; ntp < 2; ntp++)
        boff[ntp] = ((wn * 32 + ntp * 16 + ((l >> 4) & 1) * 8 + (l & 7)) * SROW
                     + ((l >> 3) & 1) * 8) * 2;

    float acc[4][4][4];
    #pragma unroll
    for (int i = 0; i < 4; i++)
        #pragma unroll
        for (int j = 0; j < 4; j++)
            #pragma unroll
            for (int q = 0; q < 4; q++) acc[i][j][q] = 0.f;

    auto load = [&](int kc) {
        char* base = sm + (kc & 1) * STAGEB;
        const bool first = kc < NC1;
        const int kco = first ? kc : kc - NC1;
        const __half* xf = (first ? XfB : Xf2B) + kco * 32;
        const __half* wh = WhB + kc * 32;
        const __half* wl = WlB + kc * 32;
        #pragma unroll
        for (int i = 0; i < 2; i++) {
            int s = tid * 2 + i;
            int row = s >> 2, seg = s & 3;
            uint32_t d0 = smem_u32(base + row * (SROW * 2) + seg * 16);
            CP_ASYNC16(d0,            wh + (size_t)row * Cin  + seg * 8);
            CP_ASYNC16(d0 + MATB,     wl + (size_t)row * Cin  + seg * 8);
            CP_ASYNC16(d0 + 2 * MATB, xf + (size_t)row * CinB + seg * 8);
        }
        CP_COMMIT();
    };

    load(0);
    for (int kc = 0; kc < NC; kc++) {
        if (kc + 1 < NC) { load(kc + 1); CP_WAIT(1); }
        else            { CP_WAIT(0); }
        __syncthreads();

        const uint32_t S = sbase + (kc & 1) * STAGEB;
        #pragma unroll
        for (int ks = 0; ks < 2; ks++) {
            unsigned fa[4][4], fb[2][4];
            #pragma unroll
            for (int mt = 0; mt < 4; mt++) LDM4(fa[mt], S + aoff[mt] + ks * 32);
            #pragma unroll
            for (int p = 0; p < 2; p++)
                LDM4(fb[p], S + 2 * MATB + boff[p] + ks * 32);
            // W_hi x X
            #pragma unroll
            for (int mt = 0; mt < 4; mt++)
                #pragma unroll
                for (int nt = 0; nt < 4; nt++)
                    MMA_FP16(acc[mt][nt], fa[mt], fb[nt >> 1][(nt & 1) * 2],
                             fb[nt >> 1][(nt & 1) * 2 + 1]);
            // W_lo x X
            #pragma unroll
            for (int mt = 0; mt < 4; mt++) LDM4(fa[mt], S + MATB + aoff[mt] + ks * 32);
            #pragma unroll
            for (int mt = 0; mt < 4; mt++)
                #pragma unroll
                for (int nt = 0; nt < 4; nt++)
                    MMA_FP16(acc[mt][nt], fa[mt], fb[nt >> 1][(nt & 1) * 2],
                             fb[nt >> 1][(nt & 1) * 2 + 1]);
        }
        __syncthreads();
    }

    // ---------------- epilogue ----------------
    #pragma unroll
    for (int mt = 0; mt < 4; mt++) {
        int o1 = o0 + wm * 64 + mt * 16 + (l >> 2);
        int o2 = o1 + 8;
        float b1v = bias[o1], b2v = bias[o2];
        float sc1 = 1.f, sh1 = 0.f, sc2 = 1.f, sh2 = 0.f;
        if (EPI == 1) {
            float s1 = g[o1] * rsqrtf(var[o1] + 1e-5f);
            sc1 = s1; sh1 = bt[o1] - mu[o1] * s1;
            float s2 = g[o2] * rsqrtf(var[o2] + 1e-5f);
            sc2 = s2; sh2 = bt[o2] - mu[o2] * s2;
        }
        size_t r1i = ((size_t)b * Cout + o1) * NSEQ + n0 + wn * 32;
        size_t r2i = ((size_t)b * Cout + o2) * NSEQ + n0 + wn * 32;
        #pragma unroll
        for (int nt = 0; nt < 4; nt++) {
            int nn = nt * 8 + (l & 3) * 2;
            float v0 = acc[mt][nt][0] + b1v, v1 = acc[mt][nt][1] + b1v;
            float v2 = acc[mt][nt][2] + b2v, v3 = acc[mt][nt][3] + b2v;
            if (EPI == 1) {
                v0 = fmaxf(fmaf(v0, sc1, sh1), 0.f); v1 = fmaxf(fmaf(v1, sc1, sh1), 0.f);
                v2 = fmaxf(fmaf(v2, sc2, sh2), 0.f); v3 = fmaxf(fmaf(v3, sc2, sh2), 0.f);
            }
            if (EPI == 2) {
                float2 ra = *(const float2*)(res + r1i + nn);
                float2 rb = *(const float2*)(res + r2i + nn);
                v0 += ra.x; v1 += ra.y; v2 += rb.x; v3 += rb.y;
            }
            if (EPI == 3) {
                // bf16 hi/lo split output (consumed by flash at 3-pass bf16)
                __nv_bfloat16 h0 = __float2bfloat16(v0), h1 = __float2bfloat16(v1);
                __nv_bfloat16 h2 = __float2bfloat16(v2), h3 = __float2bfloat16(v3);
                uint32_t H1 = (uint32_t)__bfloat16_as_ushort(h0) | ((uint32_t)__bfloat16_as_ushort(h1) << 16);
                uint32_t H2 = (uint32_t)__bfloat16_as_ushort(h2) | ((uint32_t)__bfloat16_as_ushort(h3) << 16);
                uint32_t L1 = packbf(v0 - __bfloat162float(h0), v1 - __bfloat162float(h1));
                uint32_t L2 = packbf(v2 - __bfloat162float(h2), v3 - __bfloat162float(h3));
                *(uint32_t*)(outH + r1i + nn) = H1;
                *(uint32_t*)(outH + r2i + nn) = H2;
                *(uint32_t*)(outL + r1i + nn) = L1;
                *(uint32_t*)(outL + r2i + nn) = L2;
            } else {
                *(float2*)(out + r1i + nn) = make_float2(v0, v1);
                *(float2*)(out + r2i + nn) = make_float2(v2, v3);
            }
        }
    }
}

// ======================= flash attention (mma.sync, bf16 3x split — unchanged math) ====
// QKV combined: [b][3D: q|k|v][n] bf16 hi/lo, per head [dk][n].
// Output: [b][n][h*64+dk] SINGLE fp16 (feeds fp16 merged GEMM).
#define FSROW 136
#define FROWB (FSROW * 2)        // 272 B
#define FMATB (64 * FROWB)       // 17408 B
#define FSMEM (10 * FMATB)       // 174080 B

__global__ __launch_bounds__(256, 1) void flash_k(
    const __nv_bfloat16* __restrict__ QKVh, const __nv_bfloat16* __restrict__ QKVl,
    __half* __restrict__ O)
{
    extern __shared__ __align__(16) char sm[];
    const int tid = threadIdx.x, l = tid & 31, w = tid >> 5;
    const int n0 = blockIdx.x * 128;
    const int bh = blockIdx.y;
    const int b = bh >> 4, h = bh & 15;
    const size_t qbase = ((size_t)b * 3 * DIM + h * 64) * NSEQ;
    const size_t kbase = qbase + (size_t)DIM * NSEQ;
    const size_t vbase = kbase + (size_t)DIM * NSEQ;
    const uint32_t sb = smem_u32(sm);

    // ---- q load ----
    {
        const __nv_bfloat16* srcs[2] = {QKVh + qbase + n0, QKVl + qbase + n0};
        #pragma unroll
        for (int m4 = 0; m4 < 2; m4++)
            #pragma unroll
            for (int i = 0; i < 4; i++) {
                int idx = tid + i * 256;
                int row = idx >> 4, seg = idx & 15;
                CP_ASYNC16(sb + m4 * FMATB + row * FROWB + seg * 16,
                           (const char*)(srcs[m4] + (size_t)row * NSEQ) + seg * 16);
            }
    }
    auto load_kv = [&](int kc) {
        int m0 = kc * 128;
        const __nv_bfloat16* srcs[4] = {QKVh + kbase + m0, QKVl + kbase + m0,
                                        QKVh + vbase + m0, QKVl + vbase + m0};
        uint32_t stg = sb + 2 * FMATB + (kc & 1) * 4 * FMATB;
        #pragma unroll
        for (int m4 = 0; m4 < 4; m4++)
            #pragma unroll
            for (int i = 0; i < 4; i++) {
                int idx = tid + i * 256;
                int row = idx >> 4, seg = idx & 15;
                CP_ASYNC16(stg + m4 * FMATB + row * FROWB + seg * 16,
                           (const char*)(srcs[m4] + (size_t)row * NSEQ) + seg * 16);
            }
    };
    load_kv(0); CP_COMMIT();
    load_kv(1); CP_COMMIT();
    CP_WAIT(1); __syncthreads();

    // ---- preload Q a-frags ----
    unsigned qfh[4][4], qfl[4][4];
    {
        int row_in = ((l >> 4) & 1) * 8 + (l & 7);
        int col = w * 16 + ((l >> 3) & 1) * 8;
        #pragma unroll
        for (int ks = 0; ks < 4; ks++) {
            uint32_t a = sb + (ks * 16 + row_in) * FROWB + col * 2;
            LDM4T(qfh[ks], a);
            LDM4T(qfl[ks], a + FMATB);
        }
    }

    float Oacc[8][4];
    #pragma unroll
    for (int u = 0; u < 8; u++)
        #pragma unroll
        for (int q = 0; q < 4; q++) Oacc[u][q] = 0.f;
    float rm0 = -1e30f, rm1 = -1e30f, rs0 = 0.f, rs1 = 0.f;

    const int krow = ((l >> 3) & 1) * 8 + (l & 7);
    const int kcol = ((l >> 4) & 1) * 8;
    const int vrow = ((l >> 4) & 1) * 8 + (l & 7);
    const int vcol = ((l >> 3) & 1) * 8;

    for (int kc = 0; kc < 8; kc++) {
        uint32_t stg = sb + 2 * FMATB + (kc & 1) * 4 * FMATB;

        float sacc[16][4];
        #pragma unroll
        for (int t = 0; t < 16; t++)
            #pragma unroll
            for (int q = 0; q < 4; q++) sacc[t][q] = 0.f;

        #pragma unroll
        for (int j = 0; j < 8; j++) {
            #pragma unroll
            for (int ks = 0; ks < 4; ks++) {
                unsigned bh4[4], bl4[4];
                uint32_t a = stg + (ks * 16 + krow) * FROWB + (j * 16 + kcol) * 2;
                LDM4T(bh4, a);
                LDM4T(bl4, a + FMATB);
                MMA_BF16(sacc[2 * j],     qfh[ks], bh4[0], bh4[1]);
                MMA_BF16(sacc[2 * j + 1], qfh[ks], bh4[2], bh4[3]);
                MMA_BF16(sacc[2 * j],     qfh[ks], bl4[0], bl4[1]);
                MMA_BF16(sacc[2 * j + 1], qfh[ks], bl4[2], bl4[3]);
                MMA_BF16(sacc[2 * j],     qfl[ks], bh4[0], bh4[1]);
                MMA_BF16(sacc[2 * j + 1], qfl[ks], bh4[2], bh4[3]);
            }
        }

        // ---- online softmax ----
        float cm0 = -1e30f, cm1 = -1e30f;
        #pragma unroll
        for (int t = 0; t < 16; t++) {
            sacc[t][0] *= 0.125f; sacc[t][1] *= 0.125f;
            sacc[t][2] *= 0.125f; sacc[t][3] *= 0.125f;
            cm0 = fmaxf(cm0, fmaxf(sacc[t][0], sacc[t][1]));
            cm1 = fmaxf(cm1, fmaxf(sacc[t][2], sacc[t][3]));
        }
        cm0 = fmaxf(cm0, __shfl_xor_sync(0xffffffffu, cm0, 1));
        cm0 = fmaxf(cm0, __shfl_xor_sync(0xffffffffu, cm0, 2));
        cm1 = fmaxf(cm1, __shfl_xor_sync(0xffffffffu, cm1, 1));
        cm1 = fmaxf(cm1, __shfl_xor_sync(0xffffffffu, cm1, 2));
        float nm0 = fmaxf(rm0, cm0), nm1 = fmaxf(rm1, cm1);
        float al0 = __expf(rm0 - nm0), al1 = __expf(rm1 - nm1);
        rm0 = nm0; rm1 = nm1;

        float cs0 = 0.f, cs1 = 0.f;
        #pragma unroll
        for (int t = 0; t < 16; t++) {
            sacc[t][0] = __expf(sacc[t][0] - nm0);
            sacc[t][1] = __expf(sacc[t][1] - nm0);
            sacc[t][2] = __expf(sacc[t][2] - nm1);
            sacc[t][3] = __expf(sacc[t][3] - nm1);
            cs0 += sacc[t][0] + sacc[t][1];
            cs1 += sacc[t][2] + sacc[t][3];
        }
        cs0 += __shfl_xor_sync(0xffffffffu, cs0, 1);
        cs0 += __shfl_xor_sync(0xffffffffu, cs0, 2);
        cs1 += __shfl_xor_sync(0xffffffffu, cs1, 1);
        cs1 += __shfl_xor_sync(0xffffffffu, cs1, 2);
        rs0 = rs0 * al0 + cs0;
        rs1 = rs1 * al1 + cs1;
        #pragma unroll
        for (int u = 0; u < 8; u++) {
            Oacc[u][0] *= al0; Oacc[u][1] *= al0;
            Oacc[u][2] *= al1; Oacc[u][3] *= al1;
        }

        // ---- O += P V ----
        #pragma unroll
        for (int kk = 0; kk < 8; kk++) {
            unsigned pfh[4], pfl[4];
            {
                float p0 = sacc[2 * kk][0],     p1 = sacc[2 * kk][1];
                float p2 = sacc[2 * kk][2],     p3 = sacc[2 * kk][3];
                float p4 = sacc[2 * kk + 1][0], p5 = sacc[2 * kk + 1][1];
                float p6 = sacc[2 * kk + 1][2], p7 = sacc[2 * kk + 1][3];
                __nv_bfloat16 h0 = __float2bfloat16(p0), h1 = __float2bfloat16(p1);
                __nv_bfloat16 h2 = __float2bfloat16(p2), h3 = __float2bfloat16(p3);
                __nv_bfloat16 h4 = __float2bfloat16(p4), h5 = __float2bfloat16(p5);
                __nv_bfloat16 h6 = __float2bfloat16(p6), h7 = __float2bfloat16(p7);
                pfh[0] = (uint32_t)__bfloat16_as_ushort(h0) | ((uint32_t)__bfloat16_as_ushort(h1) << 16);
                pfh[1] = (uint32_t)__bfloat16_as_ushort(h2) | ((uint32_t)__bfloat16_as_ushort(h3) << 16);
                pfh[2] = (uint32_t)__bfloat16_as_ushort(h4) | ((uint32_t)__bfloat16_as_ushort(h5) << 16);
                pfh[3] = (uint32_t)__bfloat16_as_ushort(h6) | ((uint32_t)__bfloat16_as_ushort(h7) << 16);
                pfl[0] = packbf(p0 - __bfloat162float(h0), p1 - __bfloat162float(h1));
                pfl[1] = packbf(p2 - __bfloat162float(h2), p3 - __bfloat162float(h3));
                pfl[2] = packbf(p4 - __bfloat162float(h4), p5 - __bfloat162float(h5));
                pfl[3] = packbf(p6 - __bfloat162float(h6), p7 - __bfloat162float(h7));
            }
            #pragma unroll
            for (int t = 0; t < 4; t++) {
                unsigned vh4[4], vl4[4];
                uint32_t a = stg + 2 * FMATB + (t * 16 + vrow) * FROWB + (kk * 16 + vcol) * 2;
                LDM4(vh4, a);
                LDM4(vl4, a + FMATB);
                MMA_BF16(Oacc[2 * t],     pfh, vh4[0], vh4[1]);
                MMA_BF16(Oacc[2 * t + 1], pfh, vh4[2], vh4[3]);
                MMA_BF16(Oacc[2 * t],     pfl, vh4[0], vh4[1]);
                MMA_BF16(Oacc[2 * t + 1], pfl, vh4[2], vh4[3]);
                MMA_BF16(Oacc[2 * t],     pfh, vl4[0], vl4[1]);
                MMA_BF16(Oacc[2 * t + 1], pfh, vl4[2], vl4[3]);
            }
        }
        __syncthreads();
        if (kc + 2 < 8) {
            load_kv(kc + 2); CP_COMMIT();
            CP_WAIT(1); __syncthreads();
        } else if (kc + 1 < 8) {
            CP_WAIT(0); __syncthreads();
        }
    }

    // ---- finalize: single fp16 out [b][n][h*64+dk] ----
    float inv0 = 1.f / rs0, inv1 = 1.f / rs1;
    int nr0 = n0 + w * 16 + (l >> 2);
    int nr1 = nr0 + 8;
    size_t base0 = ((size_t)b * NSEQ + nr0) * DIM + h * 64;
    size_t base1 = ((size_t)b * NSEQ + nr1) * DIM + h * 64;
    #pragma unroll
    for (int u = 0; u < 8; u++) {
        int dk = u * 8 + 2 * (l & 3);
        *(uint32_t*)(O + base0 + dk) = packh(Oacc[u][0] * inv0, Oacc[u][1] * inv0);
        *(uint32_t*)(O + base1 + dk) = packh(Oacc[u][2] * inv1, Oacc[u][3] * inv1);
    }
}

// ======================= weight split kernels (fp16 hi/lo) =======================
__global__ __launch_bounds__(256) void splitH_k(
    const float* __restrict__ src, __half* __restrict__ hi,
    __half* __restrict__ lo, int n4)
{
    int i = blockIdx.x * 256 + threadIdx.x;
    if (i >= n4) return;
    float4 v = ((const float4*)src)[i];
    __half hx = __float2half(v.x), hy = __float2half(v.y);
    __half hz = __float2half(v.z), hw = __float2half(v.w);
    uint2 H, L;
    H.x = (uint32_t)__half_as_ushort(hx) | ((uint32_t)__half_as_ushort(hy) << 16);
    H.y = (uint32_t)__half_as_ushort(hz) | ((uint32_t)__half_as_ushort(hw) << 16);
    L.x = packh(v.x - __half2float(hx), v.y - __half2float(hy));
    L.y = packh(v.z - __half2float(hz), v.w - __half2float(hw));
    ((uint2*)hi)[i] = H;
    ((uint2*)lo)[i] = L;
}

// row-permuted split into combined QKV buffer region `reg`:
// dst[layer][reg*D + o'][c],  o' = h*64+dk  <-  src[layer][dk*16+h][c]
__global__ __launch_bounds__(256) void split_permR_k(
    const float* __restrict__ src, __half* __restrict__ hi,
    __half* __restrict__ lo, int reg)
{
    int i = blockIdx.x * 256 + threadIdx.x;      // over L*D*(D/4)
    int row = i / (DIM / 4), c4 = i % (DIM / 4);
    int layer = row / DIM, op = row % DIM;
    int o = ((op & 63) << 4) + (op >> 6);
    float4 v = ((const float4*)src)[((size_t)layer * DIM + o) * (DIM / 4) + c4];
    __half hx = __float2half(v.x), hy = __float2half(v.y);
    __half hz = __float2half(v.z), hw = __float2half(v.w);
    uint2 H, L;
    H.x = (uint32_t)__half_as_ushort(hx) | ((uint32_t)__half_as_ushort(hy) << 16);
    H.y = (uint32_t)__half_as_ushort(hz) | ((uint32_t)__half_as_ushort(hw) << 16);
    L.x = packh(v.x - __half2float(hx), v.y - __half2float(hy));
    L.y = packh(v.z - __half2float(hz), v.w - __half2float(hw));
    size_t j = (((size_t)layer * 3 + reg) * DIM + op) * (DIM / 4) + c4;
    ((uint2*)hi)[j] = H;
    ((uint2*)lo)[j] = L;
}

// col-permuted split: out[layer, o, c'=h*64+dk] = in[layer, o, dk*16+h]
__global__ __launch_bounds__(256) void split_permC_k(
    const float* __restrict__ src, __half* __restrict__ hi,
    __half* __restrict__ lo)
{
    int i = blockIdx.x * 256 + threadIdx.x;
    int row = i / DIM, cp = i % DIM;
    int c = ((cp & 63) << 4) + (cp >> 6);
    float v = src[(size_t)row * DIM + c];
    __half hv = __float2half(v);
    hi[i] = hv;
    lo[i] = __float2half(v - __half2float(hv));
}

__global__ __launch_bounds__(256) void permB_k(
    const float* __restrict__ src, float* __restrict__ dst, int reg)
{
    int i = blockIdx.x * 256 + threadIdx.x;      // over L*D
    int layer = i / DIM, op = i % DIM;
    dst[((size_t)layer * 3 + reg) * DIM + op] =
        src[layer * DIM + ((op & 63) << 4) + (op >> 6)];
}

// ======================= transpose: fp32 (b,c,n) -> single fp16 (b,n,C) ============
__global__ __launch_bounds__(256) void transposeS_k(
    const float* __restrict__ src, __half* __restrict__ dst,
    int C, int dstStride, int dstOff)
{
    __shared__ float t[32][33];
    const int b  = blockIdx.z;
    const int n0 = blockIdx.x * 32;
    const int c0 = blockIdx.y * 32;
    const float* s = src + (size_t)b * C * NSEQ;
    const size_t dbase = (size_t)b * NSEQ * dstStride + dstOff;
    const int tx = threadIdx.x & 31, ty = threadIdx.x >> 5;
    #pragma unroll
    for (int i = 0; i < 32; i += 8)
        t[ty + i][tx] = s[(size_t)(c0 + ty + i) * NSEQ + n0 + tx];
    __syncthreads();
    #pragma unroll
    for (int i = 0; i < 32; i += 8) {
        size_t idx = dbase + (size_t)(n0 + ty + i) * dstStride + c0 + tx;
        dst[idx] = __float2half(t[tx][ty + i]);
    }
}

// ======================= host launcher =======================
extern "C" void kernel_launch(void* const* d_in, const int* in_sizes, int n_in,
                              void* d_out, int out_size)
{
    const float* motion = (const float*)d_in[0];
    const float* Wq  = (const float*)d_in[1];
    const float* bq  = (const float*)d_in[2];
    const float* Wk  = (const float*)d_in[3];
    const float* bk  = (const float*)d_in[4];
    const float* Wv  = (const float*)d_in[5];
    const float* bv  = (const float*)d_in[6];
    const float* Wm  = (const float*)d_in[7];
    const float* bm  = (const float*)d_in[8];
    const float* Wp1 = (const float*)d_in[9];
    const float* bp1 = (const float*)d_in[10];
    const float* bng = (const float*)d_in[11];
    const float* bnb = (const float*)d_in[12];
    const float* bnm = (const float*)d_in[13];
    const float* bnv = (const float*)d_in[14];
    const float* Wp2 = (const float*)d_in[15];
    const float* bp2 = (const float*)d_in[16];

    float *xb, *mb, *hb, *bqkvP;
    cudaGetSymbolAddress((void**)&xb, g_x);
    cudaGetSymbolAddress((void**)&mb, g_m);
    cudaGetSymbolAddress((void**)&hb, g_h);
    cudaGetSymbolAddress((void**)&bqkvP, g_bqkvP);

    __half *Wqkvh, *Wqkvl, *Wmh, *Wml, *Wp1h, *Wp1l, *Wp2h, *Wp2l;
    __half *xT, *aT, *mT, *hT;
    __nv_bfloat16 *qkvh, *qkvl;
    cudaGetSymbolAddress((void**)&Wqkvh, g_Wqkvh); cudaGetSymbolAddress((void**)&Wqkvl, g_Wqkvl);
    cudaGetSymbolAddress((void**)&Wmh, g_Wmh);     cudaGetSymbolAddress((void**)&Wml, g_Wml);
    cudaGetSymbolAddress((void**)&Wp1h, g_Wp1h);   cudaGetSymbolAddress((void**)&Wp1l, g_Wp1l);
    cudaGetSymbolAddress((void**)&Wp2h, g_Wp2h);   cudaGetSymbolAddress((void**)&Wp2l, g_Wp2l);
    cudaGetSymbolAddress((void**)&xT, g_xT);
    cudaGetSymbolAddress((void**)&aT, g_aT);
    cudaGetSymbolAddress((void**)&mT, g_mT);
    cudaGetSymbolAddress((void**)&hT, g_hT);
    cudaGetSymbolAddress((void**)&qkvh, g_qkvh);   cudaGetSymbolAddress((void**)&qkvl, g_qkvl);

    cudaFuncSetAttribute(gemmt_k<0>, cudaFuncAttributeMaxDynamicSharedMemorySize, GSMEM);
    cudaFuncSetAttribute(gemmt_k<1>, cudaFuncAttributeMaxDynamicSharedMemorySize, GSMEM);
    cudaFuncSetAttribute(gemmt_k<2>, cudaFuncAttributeMaxDynamicSharedMemorySize, GSMEM);
    cudaFuncSetAttribute(gemmt_k<3>, cudaFuncAttributeMaxDynamicSharedMemorySize, GSMEM);
    cudaFuncSetAttribute(flash_k, cudaFuncAttributeMaxDynamicSharedMemorySize, FSMEM);

    cudaMemcpyAsync(xb, motion, (size_t)BATCH * DIM * NSEQ * sizeof(float),
                    cudaMemcpyDeviceToDevice);

    // ---- weight prep ----
    const int nW  = LAYERS * DIM * DIM;
    const int nP1 = LAYERS * 2 * DIM * 2 * DIM;
    const int nP2 = LAYERS * DIM * 2 * DIM;
    split_permR_k<<<nW / 4 / 256, 256>>>(Wq, Wqkvh, Wqkvl, 0);
    split_permR_k<<<nW / 4 / 256, 256>>>(Wk, Wqkvh, Wqkvl, 1);
    split_permR_k<<<nW / 4 / 256, 256>>>(Wv, Wqkvh, Wqkvl, 2);
    split_permC_k<<<nW / 256, 256>>>(Wm, Wmh, Wml);
    splitH_k<<<(nP1 / 4 + 255) / 256, 256>>>(Wp1, Wp1h, Wp1l, nP1 / 4);
    splitH_k<<<(nP2 / 4 + 255) / 256, 256>>>(Wp2, Wp2h, Wp2l, nP2 / 4);
    permB_k<<<LAYERS * DIM / 256, 256>>>(bq, bqkvP, 0);
    permB_k<<<LAYERS * DIM / 256, 256>>>(bk, bqkvP, 1);
    permB_k<<<LAYERS * DIM / 256, 256>>>(bv, bqkvP, 2);

    const size_t DD  = (size_t)DIM * DIM;
    const size_t DD2 = (size_t)2 * DIM * 2 * DIM;
    const size_t DD3 = (size_t)DIM * 2 * DIM;

    dim3 gT1(NSEQ / 32, DIM / 32, BATCH);
    dim3 gT2(NSEQ / 32, 2 * DIM / 32, BATCH);
    dim3 gQKV(8, 24, BATCH);      // Cout=3072
    dim3 gGemmD(8, 8, BATCH);     // Cout=1024
    dim3 gGemm2D(8, 16, BATCH);   // Cout=2048
    dim3 gFlash(NSEQ / 128, BATCH * HEADS);

    for (int l = 0; l < LAYERS; l++) {
        transposeS_k<<<gT1, 256>>>(xb, xT, DIM, DIM, 0);

        // fused Q|K|V projection -> bf16 hi/lo [b][3D][n] (EPI3)
        gemmt_k<3><<<gQKV, 256, GSMEM>>>(
            Wqkvh + l * 3 * DD, Wqkvl + l * 3 * DD,
            xT, xT,
            bqkvP + (size_t)l * 3 * DIM, nullptr, qkvh, qkvl,
            3 * DIM, DIM, DIM, 32,
            nullptr, nullptr, nullptr, nullptr, nullptr);

        flash_k<<<gFlash, 256, FSMEM>>>(qkvh, qkvl, aT);

        gemmt_k<0><<<gGemmD, 256, GSMEM>>>(
            Wmh + l * DD, Wml + l * DD,
            aT, aT,
            bm + l * DIM, mb, nullptr, nullptr,
            DIM, DIM, DIM, 32,
            nullptr, nullptr, nullptr, nullptr, nullptr);

        transposeS_k<<<gT1, 256>>>(mb, mT, DIM, DIM, 0);

        // P1 reads concat(merged^T | x^T) from two buffers
        gemmt_k<1><<<gGemm2D, 256, GSMEM>>>(
            Wp1h + l * DD2, Wp1l + l * DD2,
            mT, xT,
            bp1 + (size_t)l * 2 * DIM, hb, nullptr, nullptr,
            2 * DIM, 2 * DIM, DIM, 32,
            bng + l * 2 * DIM, bnb + l * 2 * DIM,
            bnm + l * 2 * DIM, bnv + l * 2 * DIM, nullptr);

        transposeS_k<<<gT2, 256>>>(hb, hT, 2 * DIM, 2 * DIM, 0);

        float* dst = (l == LAYERS - 1) ? (float*)d_out : xb;
        gemmt_k<2><<<gGemmD, 256, GSMEM>>>(
            Wp2h + l * DD3, Wp2l + l * DD3,
            hT, hT,
            bp2 + l * DIM, dst, nullptr, nullptr,
            DIM, 2 * DIM, 2 * DIM, 64,
            nullptr, nullptr, nullptr, nullptr, xb);
    }
}